// round 14
// baseline (speedup 1.0000x reference)
#include <cuda_runtime.h>
#include <cstdint>

// out[N,N] = diag(ics_mask - params * r_mask), N = 12288. Pure store-bound (604 MB).
//
// FINAL KERNEL. Converged at the chip fill ceiling:
//   true fill rate = 604 MB / ~80.6 us = 7.49 TB/s = 93.7% of HBM3e spec.
// Measured path-independent across plain STG.128 / __stcs / __stwt / driver
// memset (all 80.6-81.4 us kernel time) -> LTS chip cap (~6300 B/cyc) binds,
// not the SASS store path. Traffic is irreducible (harness poisons d_out).
//
// Config: 256 threads x 4 block-strided float4 chunks (each warp store covers
// a contiguous 512 B run -> full-sector writes), one diagonal test per block
// (block span 4096 < N+1 = 12289 -> at most one hit), exact grid, no tail.

static constexpr unsigned N  = 12288u;
static constexpr unsigned N4 = (N * N) / 4u;   // 37,748,736 float4 stores

__global__ void __launch_bounds__(256) diag_fill_kernel(
    float4* __restrict__ out4,
    const float* __restrict__ params,
    const int*   __restrict__ r_mask,
    const int*   __restrict__ ics_mask)
{
    // Block owns 1024 consecutive float4s = 4096 elements [jb, jb+4096).
    unsigned jb = blockIdx.x * 4096u;

    // At most one diagonal element d = i*(N+1) per block.
    unsigned i = (jb + N) / (N + 1u);          // ceil(jb/(N+1)) -> mul+shift
    unsigned d = i * (N + 1u);
    float diagval = 0.0f;
    if (i < N && d < jb + 4096u)
        diagval = (float)ics_mask[i] - params[i] * (float)r_mask[i];

    unsigned base = blockIdx.x * 1024u + threadIdx.x;

    #pragma unroll
    for (unsigned c = 0; c < 4u; ++c) {
        unsigned f = base + c * 256u;          // float4 index, < N4 exactly
        unsigned j = f * 4u;                   // window [j, j+4)

        float4 v = make_float4(0.f, 0.f, 0.f, 0.f);
        unsigned off = d - j;                  // unsigned wrap if d < j
        if (off < 4u) {
            if      (off == 0u) v.x = diagval;
            else if (off == 1u) v.y = diagval;
            else if (off == 2u) v.z = diagval;
            else                v.w = diagval;
        }

        __stwt(out4 + f, v);                   // st.global.wt.v4, coalesced
    }
}

extern "C" void kernel_launch(void* const* d_in, const int* in_sizes, int n_in,
                              void* d_out, int out_size)
{
    const float* params   = (const float*)d_in[0];
    const int*   r_mask   = (const int*)  d_in[1];
    const int*   ics_mask = (const int*)  d_in[2];
    float4*      out4     = (float4*)d_out;

    (void)in_sizes; (void)n_in; (void)out_size;

    const unsigned threads = 256;
    const unsigned blocks  = N4 / (threads * 4u);   // 36,864 — exact, no tail
    diag_fill_kernel<<<blocks, threads>>>(out4, params, r_mask, ics_mask);
}

// round 15
// speedup vs baseline: 1.0176x; 1.0176x over previous
#include <cuda_runtime.h>
#include <cstdint>

// out[N,N] = diag(ics_mask - params * r_mask), N = 12288. Pure store-bound (604 MB).
//
// FINAL KERNEL — converged at the chip fill ceiling.
//   true fill rate = 604 MB / ~80.6 us kernel = 7.49 TB/s = 93.7% of HBM3e spec.
// Evidence of ceiling (path-independent LTS cap, ~6300 B/cyc):
//   plain STG.128   -> 81.3 us   (R5/R8)
//   __stcs STG.128  -> 80.7-81.3 us (R8/R11)
//   __stwt STG.128  -> 80.6-80.7 us (R13/R14)
//   driver memset   -> ~81 us    (R9 control)
// Traffic is irreducible (harness poisons d_out -> all 604 MB must be written).
// End-to-end spread 82.2-83.7 us is harness/replay jitter, not kernel.
//
// Config: 256 threads x 4 block-strided float4 chunks (each warp store covers a
// contiguous 512 B run -> full-sector writes), one diagonal test per block
// (block span 4096 < N+1 = 12289 -> at most one hit), exact grid, no tail.

static constexpr unsigned N  = 12288u;
static constexpr unsigned N4 = (N * N) / 4u;   // 37,748,736 float4 stores

__global__ void __launch_bounds__(256) diag_fill_kernel(
    float4* __restrict__ out4,
    const float* __restrict__ params,
    const int*   __restrict__ r_mask,
    const int*   __restrict__ ics_mask)
{
    // Block owns 1024 consecutive float4s = 4096 elements [jb, jb+4096).
    unsigned jb = blockIdx.x * 4096u;

    // At most one diagonal element d = i*(N+1) per block.
    unsigned i = (jb + N) / (N + 1u);          // ceil(jb/(N+1)) -> mul+shift
    unsigned d = i * (N + 1u);
    float diagval = 0.0f;
    if (i < N && d < jb + 4096u)
        diagval = (float)ics_mask[i] - params[i] * (float)r_mask[i];

    unsigned base = blockIdx.x * 1024u + threadIdx.x;

    #pragma unroll
    for (unsigned c = 0; c < 4u; ++c) {
        unsigned f = base + c * 256u;          // float4 index, < N4 exactly
        unsigned j = f * 4u;                   // window [j, j+4)

        float4 v = make_float4(0.f, 0.f, 0.f, 0.f);
        unsigned off = d - j;                  // unsigned wrap if d < j
        if (off < 4u) {
            if      (off == 0u) v.x = diagval;
            else if (off == 1u) v.y = diagval;
            else if (off == 2u) v.z = diagval;
            else                v.w = diagval;
        }

        __stcs(out4 + f, v);                   // st.global.cs.v4, coalesced
    }
}

extern "C" void kernel_launch(void* const* d_in, const int* in_sizes, int n_in,
                              void* d_out, int out_size)
{
    const float* params   = (const float*)d_in[0];
    const int*   r_mask   = (const int*)  d_in[1];
    const int*   ics_mask = (const int*)  d_in[2];
    float4*      out4     = (float4*)d_out;

    (void)in_sizes; (void)n_in; (void)out_size;

    const unsigned threads = 256;
    const unsigned blocks  = N4 / (threads * 4u);   // 36,864 — exact, no tail
    diag_fill_kernel<<<blocks, threads>>>(out4, params, r_mask, ics_mask);
}